// round 13
// baseline (speedup 1.0000x reference)
#include <cuda_runtime.h>
#include <math.h>

#define DIMX   20
#define DD     21
#define NPT    2048
#define MCc    32
#define UNITS  128
#define TP     16
#define BTOT   69632
#define NTILES (BTOT / TP)
#define THREADS 512

#define SIGc   0.2f
#define MUc    0.05f
#define Rc     0.05f
#define DELTAc 0.01f

__device__ float g_L[DIMX * DIMX];
__device__ float g_WT[4 * UNITS * UNITS];   // [mat][a][b] = W[b][a]
__device__ float g_UcatT[5 * UNITS * 24];   // [v][j][24] padded
__device__ float g_X[BTOT * DD];
__device__ float g_FP[BTOT * DD];
__device__ float g_FVAL[BTOT];

// smem (floats). Activation arrays are [point][unit] = [16][128].
#define SM_X    0                        // [21][16] = 336
#define SM_S    336                      // 3 * 2048
#define SM_Z    (SM_S + 3 * 2048)
#define SM_G    (SM_Z + 3 * 2048)
#define SM_R    (SM_G + 3 * 2048)
#define SM_H    (SM_R + 3 * 2048)
#define SM_SR   (SM_H + 3 * 2048)        // 2048 scratch (s*r, later dx partials)
#define SM_TOT  (SM_SR + 2048)           // 33104 floats = 132416 B

typedef unsigned long long u64t;

__device__ __forceinline__ u64t pack2(float lo, float hi) {
    u64t r;
    asm("mov.b64 %0, {%1, %2};" : "=l"(r) : "f"(lo), "f"(hi));
    return r;
}
__device__ __forceinline__ float2 unpack2(u64t v) {
    float2 f;
    asm("mov.b64 {%0, %1}, %2;" : "=f"(f.x), "=f"(f.y) : "l"(v));
    return f;
}
__device__ __forceinline__ u64t ffma2(u64t a, u64t b, u64t c) {
    u64t d;
    asm("fma.rn.f32x2 %0, %1, %2, %3;" : "=l"(d) : "l"(a), "l"(b), "l"(c));
    return d;
}
__device__ __forceinline__ float ftanh(float x) {
    float ax = fabsf(x);
    float t = __expf(-2.0f * ax);
    float r = __fdividef(1.0f - t, 1.0f + t);
    return copysignf(r, x);
}

__global__ void prep_kernel(const float* __restrict__ wz, const float* __restrict__ wg,
                            const float* __restrict__ wr, const float* __restrict__ wh,
                            const float* __restrict__ uz, const float* __restrict__ ug,
                            const float* __restrict__ ur, const float* __restrict__ uh,
                            const float* __restrict__ w1)
{
    int idx = blockIdx.x * blockDim.x + threadIdx.x;
    int stride = gridDim.x * blockDim.x;

    for (int t = idx; t < 4 * UNITS * UNITS; t += stride) {
        int mat = t >> 14;
        int r   = t & 16383;
        int a   = r >> 7;
        int b   = r & 127;
        const float* W = (mat == 0) ? wz : (mat == 1) ? wg : (mat == 2) ? wr : wh;
        g_WT[t] = W[b * UNITS + a];
    }
    for (int t = idx; t < 5 * UNITS * 24; t += stride) {
        int v = t / (UNITS * 24);
        int r = t % (UNITS * 24);
        int j = r / 24;
        int d = r % 24;
        const float* U = (v == 0) ? uz : (v == 1) ? ug : (v == 2) ? ur : (v == 3) ? uh : w1;
        g_UcatT[t] = (d < DD) ? U[d * UNITS + j] : 0.0f;
    }
    if (idx == 0) {
        double Ld[DIMX][DIMX];
        for (int i = 0; i < DIMX; i++) {
            for (int j2 = 0; j2 <= i; j2++) {
                double s = 0.01 * (0.5 + (i == j2 ? 0.5 : 0.0));
                for (int k = 0; k < j2; k++) s -= Ld[i][k] * Ld[j2][k];
                Ld[i][j2] = (i == j2) ? sqrt(s) : s / Ld[j2][j2];
            }
        }
        for (int i = 0; i < DIMX; i++)
            for (int j2 = 0; j2 < DIMX; j2++)
                g_L[i * DIMX + j2] = (j2 <= i) ? (float)Ld[i][j2] : 0.0f;
    }
}

__global__ void build_kernel(const float* __restrict__ inputs, const float* __restrict__ eps)
{
    int r = blockIdx.x * blockDim.x + threadIdx.x;
    if (r >= BTOT) return;
    if (r < 4096) {
        #pragma unroll
        for (int d = 0; d < DD; d++) g_X[r * DD + d] = inputs[r * DD + d];
    } else {
        int q = r - 4096;
        int m = q >> 11;
        int n = q & 2047;
        float xr[DD];
        #pragma unroll
        for (int d = 0; d < DD; d++) xr[d] = inputs[n * DD + d];
        float e[DIMX];
        #pragma unroll
        for (int d = 0; d < DIMX; d++) e[d] = eps[(m * NPT + n) * DIMX + d];
        #pragma unroll
        for (int k = 0; k < DIMX; k++) {
            float acc = 0.f;
            #pragma unroll
            for (int d = 0; d < DIMX; d++) acc += e[d] * g_L[k * DIMX + d];
            float sample = xr[k] + acc;
            float viol = sample * (SIGc * xr[k]);
            g_X[r * DD + k] = xr[k] + viol;
        }
        g_X[r * DD + DIMX] = xr[DIMX];
    }
}

// single-matrix pass with warp-rotated k start (miss-MLP spreading)
__device__ __forceinline__ void mm1rot(u64t& a0, u64t& a1, const float* __restrict__ W,
                                       const float* S, int j4, int prow, int koff) {
    #pragma unroll 8
    for (int k = koff; k < UNITS; k++) {
        ulonglong2 w2 = *(const ulonglong2*)&W[k * UNITS + j4];
        float sv = S[prow + k];
        u64t sp = pack2(sv, sv);
        a0 = ffma2(w2.x, sp, a0);
        a1 = ffma2(w2.y, sp, a1);
    }
    #pragma unroll 8
    for (int k = 0; k < koff; k++) {
        ulonglong2 w2 = *(const ulonglong2*)&W[k * UNITS + j4];
        float sv = S[prow + k];
        u64t sp = pack2(sv, sv);
        a0 = ffma2(w2.x, sp, a0);
        a1 = ffma2(w2.y, sp, a1);
    }
}

__global__ __launch_bounds__(THREADS, 1)
void dgm_main(const float* __restrict__ w1, const float* __restrict__ b1,
              const float* __restrict__ uz, const float* __restrict__ wz, const float* __restrict__ bz,
              const float* __restrict__ ug, const float* __restrict__ wg, const float* __restrict__ bg,
              const float* __restrict__ ur, const float* __restrict__ wr, const float* __restrict__ br,
              const float* __restrict__ uh, const float* __restrict__ wh, const float* __restrict__ bh,
              const float* __restrict__ wout, const float* __restrict__ bout)
{
    extern __shared__ float sm[];
    const int tid  = threadIdx.x;
    const int lane = tid & 31;
    const int j4   = lane * 4;          // 4 consecutive units
    const int p    = tid >> 5;          // warp id == point (0..15)
    const int prow = p * UNITS;
    const int koff = p * 8;             // rotated k start, 16 warps x 8 = 128
    const int base = blockIdx.x * TP;
    const bool doGrad = !(blockIdx.x >= 128 && blockIdx.x < 256);

    // X tile [d][p]
    for (int t = tid; t < TP * DD; t += THREADS) {
        int pp = t / DD, d = t % DD;
        sm[SM_X + d * TP + pp] = g_X[(base + pp) * DD + d];
    }
    __syncthreads();

    // ---- prologue: x@U + b for 5 matrices (thread: 4 units x 1 point) ----
    float xzv[4], xgv[4], xrv[4], xhv[4], s_cur[4];
    {
        float4 b;
        b = *(const float4*)&bz[j4]; xzv[0]=b.x; xzv[1]=b.y; xzv[2]=b.z; xzv[3]=b.w;
        b = *(const float4*)&bg[j4]; xgv[0]=b.x; xgv[1]=b.y; xgv[2]=b.z; xgv[3]=b.w;
        b = *(const float4*)&br[j4]; xrv[0]=b.x; xrv[1]=b.y; xrv[2]=b.z; xrv[3]=b.w;
        b = *(const float4*)&bh[j4]; xhv[0]=b.x; xhv[1]=b.y; xhv[2]=b.z; xhv[3]=b.w;
        b = *(const float4*)&b1[j4];
        float a1v[4] = {b.x, b.y, b.z, b.w};
        #pragma unroll 3
        for (int d = 0; d < DD; d++) {
            float xv = sm[SM_X + d * TP + p];
            float4 u;
            u = *(const float4*)&uz[d * UNITS + j4];
            xzv[0] += u.x * xv; xzv[1] += u.y * xv; xzv[2] += u.z * xv; xzv[3] += u.w * xv;
            u = *(const float4*)&ug[d * UNITS + j4];
            xgv[0] += u.x * xv; xgv[1] += u.y * xv; xgv[2] += u.z * xv; xgv[3] += u.w * xv;
            u = *(const float4*)&ur[d * UNITS + j4];
            xrv[0] += u.x * xv; xrv[1] += u.y * xv; xrv[2] += u.z * xv; xrv[3] += u.w * xv;
            u = *(const float4*)&uh[d * UNITS + j4];
            xhv[0] += u.x * xv; xhv[1] += u.y * xv; xhv[2] += u.z * xv; xhv[3] += u.w * xv;
            u = *(const float4*)&w1[d * UNITS + j4];
            a1v[0] += u.x * xv; a1v[1] += u.y * xv; a1v[2] += u.z * xv; a1v[3] += u.w * xv;
        }
        #pragma unroll
        for (int i = 0; i < 4; i++) s_cur[i] = ftanh(a1v[i]);
        *(float4*)&sm[SM_S + prow + j4] = make_float4(s_cur[0], s_cur[1], s_cur[2], s_cur[3]);
    }
    __syncthreads();

    // ---- forward ----
    #pragma unroll 1
    for (int l = 0; l < 3; l++) {
        float* Sin = &sm[SM_S + l * 2048];
        float* ZA  = &sm[SM_Z + l * 2048];
        float* GA  = &sm[SM_G + l * 2048];
        float* RA  = &sm[SM_R + l * 2048];
        float* HA  = &sm[SM_H + l * 2048];
        float* SR  = &sm[SM_SR];

        // merged z/g/r matmul, rotated k
        u64t az0 = pack2(xzv[0], xzv[1]), az1 = pack2(xzv[2], xzv[3]);
        u64t ag0 = pack2(xgv[0], xgv[1]), ag1 = pack2(xgv[2], xgv[3]);
        u64t ar0 = pack2(xrv[0], xrv[1]), ar1 = pack2(xrv[2], xrv[3]);
        #pragma unroll 4
        for (int k = koff; k < UNITS; k++) {
            ulonglong2 wz2 = *(const ulonglong2*)&wz[k * UNITS + j4];
            ulonglong2 wg2 = *(const ulonglong2*)&wg[k * UNITS + j4];
            ulonglong2 wr2 = *(const ulonglong2*)&wr[k * UNITS + j4];
            float sv = Sin[prow + k];
            u64t sp = pack2(sv, sv);
            az0 = ffma2(wz2.x, sp, az0); az1 = ffma2(wz2.y, sp, az1);
            ag0 = ffma2(wg2.x, sp, ag0); ag1 = ffma2(wg2.y, sp, ag1);
            ar0 = ffma2(wr2.x, sp, ar0); ar1 = ffma2(wr2.y, sp, ar1);
        }
        #pragma unroll 4
        for (int k = 0; k < koff; k++) {
            ulonglong2 wz2 = *(const ulonglong2*)&wz[k * UNITS + j4];
            ulonglong2 wg2 = *(const ulonglong2*)&wg[k * UNITS + j4];
            ulonglong2 wr2 = *(const ulonglong2*)&wr[k * UNITS + j4];
            float sv = Sin[prow + k];
            u64t sp = pack2(sv, sv);
            az0 = ffma2(wz2.x, sp, az0); az1 = ffma2(wz2.y, sp, az1);
            ag0 = ffma2(wg2.x, sp, ag0); ag1 = ffma2(wg2.y, sp, ag1);
            ar0 = ffma2(wr2.x, sp, ar0); ar1 = ffma2(wr2.y, sp, ar1);
        }

        float z4[4], g4[4], r4[4];
        {
            float2 t0, t1;
            t0 = unpack2(az0); t1 = unpack2(az1);
            z4[0] = ftanh(t0.x); z4[1] = ftanh(t0.y); z4[2] = ftanh(t1.x); z4[3] = ftanh(t1.y);
            t0 = unpack2(ag0); t1 = unpack2(ag1);
            g4[0] = ftanh(t0.x); g4[1] = ftanh(t0.y); g4[2] = ftanh(t1.x); g4[3] = ftanh(t1.y);
            t0 = unpack2(ar0); t1 = unpack2(ar1);
            r4[0] = ftanh(t0.x); r4[1] = ftanh(t0.y); r4[2] = ftanh(t1.x); r4[3] = ftanh(t1.y);
        }
        *(float4*)&ZA[prow + j4] = make_float4(z4[0], z4[1], z4[2], z4[3]);
        *(float4*)&GA[prow + j4] = make_float4(g4[0], g4[1], g4[2], g4[3]);
        *(float4*)&RA[prow + j4] = make_float4(r4[0], r4[1], r4[2], r4[3]);
        *(float4*)&SR[prow + j4] = make_float4(s_cur[0] * r4[0], s_cur[1] * r4[1],
                                               s_cur[2] * r4[2], s_cur[3] * r4[3]);
        __syncthreads();

        // h matmul over SR, rotated
        u64t ah0 = pack2(xhv[0], xhv[1]), ah1 = pack2(xhv[2], xhv[3]);
        mm1rot(ah0, ah1, wh, SR, j4, prow, koff);
        float h4[4];
        {
            float2 t0 = unpack2(ah0), t1 = unpack2(ah1);
            h4[0] = ftanh(t0.x); h4[1] = ftanh(t0.y); h4[2] = ftanh(t1.x); h4[3] = ftanh(t1.y);
        }
        *(float4*)&HA[prow + j4] = make_float4(h4[0], h4[1], h4[2], h4[3]);
        #pragma unroll
        for (int i = 0; i < 4; i++)
            s_cur[i] = (1.0f - g4[i]) * h4[i] + z4[i] * s_cur[i];
        if (l < 2)
            *(float4*)&sm[SM_S + (l + 1) * 2048 + prow + j4] =
                make_float4(s_cur[0], s_cur[1], s_cur[2], s_cur[3]);
        __syncthreads();
    }

    // ---- value: warp owns all units of its point ----
    float4 wo4 = *(const float4*)&wout[j4];
    {
        float v = wo4.x * s_cur[0] + wo4.y * s_cur[1] + wo4.z * s_cur[2] + wo4.w * s_cur[3];
        #pragma unroll
        for (int off = 16; off; off >>= 1) v += __shfl_xor_sync(0xffffffffu, v, off);
        if (lane == 0) g_FVAL[base + p] = v + bout[0];
    }

    if (!doGrad) return;

    // ---- backward ----
    float ds[4], Daz[4], Dag[4], Dar[4], Dah[4];
    {
        float wv[4] = {wo4.x, wo4.y, wo4.z, wo4.w};
        #pragma unroll
        for (int i = 0; i < 4; i++) {
            ds[i] = wv[i];
            Daz[i] = 0.f; Dag[i] = 0.f; Dar[i] = 0.f; Dah[i] = 0.f;
        }
    }

    #pragma unroll 1
    for (int l = 2; l >= 0; l--) {
        float* Sin = &sm[SM_S + l * 2048];
        float* ZA  = &sm[SM_Z + l * 2048];
        float* GA  = &sm[SM_G + l * 2048];
        float* RA  = &sm[SM_R + l * 2048];
        float* HA  = &sm[SM_H + l * 2048];

        // stage A: elementwise; overwrite Z/G/H with daz/dag/dah
        {
            int row = prow + j4;
            float4 zq = *(const float4*)&ZA[row];
            float4 gq = *(const float4*)&GA[row];
            float4 hq = *(const float4*)&HA[row];
            float4 sq = *(const float4*)&Sin[row];
            float zs[4] = {zq.x, zq.y, zq.z, zq.w};
            float gs[4] = {gq.x, gq.y, gq.z, gq.w};
            float hs[4] = {hq.x, hq.y, hq.z, hq.w};
            float ss[4] = {sq.x, sq.y, sq.z, sq.w};
            float dazv[4], dagv[4], dahv[4];
            #pragma unroll
            for (int i = 0; i < 4; i++) {
                float dsp = ds[i];
                float dh = dsp * (1.0f - gs[i]);
                float dg = -dsp * hs[i];
                float dz = dsp * ss[i];
                dazv[i] = dz * (1.0f - zs[i] * zs[i]);
                dagv[i] = dg * (1.0f - gs[i] * gs[i]);
                dahv[i] = dh * (1.0f - hs[i] * hs[i]);
                Daz[i] += dazv[i]; Dag[i] += dagv[i]; Dah[i] += dahv[i];
                ds[i] = dsp * zs[i];
            }
            *(float4*)&ZA[row] = make_float4(dazv[0], dazv[1], dazv[2], dazv[3]);
            *(float4*)&GA[row] = make_float4(dagv[0], dagv[1], dagv[2], dagv[3]);
            *(float4*)&HA[row] = make_float4(dahv[0], dahv[1], dahv[2], dahv[3]);
        }
        __syncthreads();

        // stage B: dsr = dah @ Wh^T, rotated
        float dsr[4];
        {
            u64t b0 = pack2(0.f, 0.f), b1p = pack2(0.f, 0.f);
            mm1rot(b0, b1p, g_WT + 3 * UNITS * UNITS, HA, j4, prow, koff);
            float2 t0 = unpack2(b0), t1 = unpack2(b1p);
            dsr[0] = t0.x; dsr[1] = t0.y; dsr[2] = t1.x; dsr[3] = t1.y;
        }

        // stage C: dar; overwrite R
        {
            int row = prow + j4;
            float4 rq = *(const float4*)&RA[row];
            float4 sq = *(const float4*)&Sin[row];
            float rs[4] = {rq.x, rq.y, rq.z, rq.w};
            float ss[4] = {sq.x, sq.y, sq.z, sq.w};
            float darv[4];
            #pragma unroll
            for (int i = 0; i < 4; i++) {
                ds[i] += dsr[i] * rs[i];
                darv[i] = (dsr[i] * ss[i]) * (1.0f - rs[i] * rs[i]);
                Dar[i] += darv[i];
            }
            *(float4*)&RA[row] = make_float4(darv[0], darv[1], darv[2], darv[3]);
        }
        __syncthreads();

        // stage D: ds += daz@Wz^T + dag@Wg^T + dar@Wr^T, merged, rotated
        {
            const float* WzT = g_WT + 0 * UNITS * UNITS;
            const float* WgT = g_WT + 1 * UNITS * UNITS;
            const float* WrT = g_WT + 2 * UNITS * UNITS;
            u64t d0 = pack2(ds[0], ds[1]), d1 = pack2(ds[2], ds[3]);
            #pragma unroll 4
            for (int k = koff; k < UNITS; k++) {
                ulonglong2 wzt = *(const ulonglong2*)&WzT[k * UNITS + j4];
                ulonglong2 wgt = *(const ulonglong2*)&WgT[k * UNITS + j4];
                ulonglong2 wrt = *(const ulonglong2*)&WrT[k * UNITS + j4];
                float zv = ZA[prow + k], gv = GA[prow + k], rv = RA[prow + k];
                u64t zp = pack2(zv, zv), gp = pack2(gv, gv), rp2 = pack2(rv, rv);
                d0 = ffma2(wzt.x, zp, d0); d1 = ffma2(wzt.y, zp, d1);
                d0 = ffma2(wgt.x, gp, d0); d1 = ffma2(wgt.y, gp, d1);
                d0 = ffma2(wrt.x, rp2, d0); d1 = ffma2(wrt.y, rp2, d1);
            }
            #pragma unroll 4
            for (int k = 0; k < koff; k++) {
                ulonglong2 wzt = *(const ulonglong2*)&WzT[k * UNITS + j4];
                ulonglong2 wgt = *(const ulonglong2*)&WgT[k * UNITS + j4];
                ulonglong2 wrt = *(const ulonglong2*)&WrT[k * UNITS + j4];
                float zv = ZA[prow + k], gv = GA[prow + k], rv = RA[prow + k];
                u64t zp = pack2(zv, zv), gp = pack2(gv, gv), rp2 = pack2(rv, rv);
                d0 = ffma2(wzt.x, zp, d0); d1 = ffma2(wzt.y, zp, d1);
                d0 = ffma2(wgt.x, gp, d0); d1 = ffma2(wgt.y, gp, d1);
                d0 = ffma2(wrt.x, rp2, d0); d1 = ffma2(wrt.y, rp2, d1);
            }
            float2 t0 = unpack2(d0), t1 = unpack2(d1);
            ds[0] = t0.x; ds[1] = t0.y; ds[2] = t1.x; ds[3] = t1.y;
        }
        // next stage A writes only layer l-1 arrays at own row: no barrier needed
    }

    // stage D(0) readers must finish before overwriting layer-0 slots
    __syncthreads();
    {
        int row = prow + j4;
        float4 sq = *(const float4*)&sm[SM_S + row];
        float s0s[4] = {sq.x, sq.y, sq.z, sq.w};
        float da1[4];
        #pragma unroll
        for (int i = 0; i < 4; i++) da1[i] = ds[i] * (1.0f - s0s[i] * s0s[i]);
        *(float4*)&sm[SM_Z + row] = make_float4(Daz[0], Daz[1], Daz[2], Daz[3]);
        *(float4*)&sm[SM_G + row] = make_float4(Dag[0], Dag[1], Dag[2], Dag[3]);
        *(float4*)&sm[SM_R + row] = make_float4(Dar[0], Dar[1], Dar[2], Dar[3]);
        *(float4*)&sm[SM_H + row] = make_float4(Dah[0], Dah[1], Dah[2], Dah[3]);
        *(float4*)&sm[SM_S + row] = make_float4(da1[0], da1[1], da1[2], da1[3]);
    }
    __syncthreads();

    // dx stage 1: partials over (p, d-quad, v) -> scratch in SM_SR
    if (tid < 480) {
        int v  = tid % 5;
        int dq = (tid / 5) % 6;
        int pp = tid / 30;
        int d0 = dq * 4;
        const float* slot =
            (v == 0) ? &sm[SM_Z] : (v == 1) ? &sm[SM_G] :
            (v == 2) ? &sm[SM_R] : (v == 3) ? &sm[SM_H] : &sm[SM_S];
        const float* Ut = g_UcatT + v * UNITS * 24;
        float acc[4] = {0.f, 0.f, 0.f, 0.f};
        #pragma unroll 8
        for (int k = 0; k < UNITS; k++) {
            float a = slot[pp * UNITS + k];
            float4 u = *(const float4*)&Ut[k * 24 + d0];
            acc[0] += a * u.x; acc[1] += a * u.y; acc[2] += a * u.z; acc[3] += a * u.w;
        }
        *(float4*)&sm[SM_SR + ((pp * 6 + dq) * 5 + v) * 4] = make_float4(acc[0], acc[1], acc[2], acc[3]);
    }
    __syncthreads();

    // dx stage 2: combine
    if (tid < 96) {
        int pp = tid / 6;
        int dq = tid % 6;
        int d0 = dq * 4;
        float acc[4] = {0.f, 0.f, 0.f, 0.f};
        #pragma unroll
        for (int v = 0; v < 5; v++) {
            float4 t = *(const float4*)&sm[SM_SR + ((pp * 6 + dq) * 5 + v) * 4];
            acc[0] += t.x; acc[1] += t.y; acc[2] += t.z; acc[3] += t.w;
        }
        #pragma unroll
        for (int i = 0; i < 4; i++) {
            int d = d0 + i;
            if (d < DD) g_FP[(base + pp) * DD + d] = acc[i];
        }
    }
}

__global__ void epilogue_kernel(float* __restrict__ out)
{
    int warpId = threadIdx.x >> 5;
    int lane   = threadIdx.x & 31;
    int n = blockIdx.x * 8 + warpId;
    if (n >= NPT) return;

    const float* fp1 = &g_FP[n * DD];
    const float* x1r = &g_X[n * DD];
    int rp = (4096 + lane * NPT + n) * DD;
    const float* fpp = &g_FP[rp];
    const float* xp  = &g_X[rp];

    float part = 0.f;
    #pragma unroll
    for (int k = 0; k < DIMX; k++) {
        float viol = xp[k] - x1r[k];
        part += (fpp[k] - fp1[k]) * viol;
    }
    #pragma unroll
    for (int off = 16; off; off >>= 1) part += __shfl_xor_sync(0xffffffffu, part, off);

    if (lane == 0) {
        float term12 = part / (DELTAc * (float)MCc);
        float term11 = fp1[DIMX];
        #pragma unroll
        for (int k = 0; k < DIMX; k++) term11 += MUc * x1r[k] * fp1[k];
        out[n] = term11 + 0.5f * term12 - Rc * g_FVAL[n];

        const float* x2r = &g_X[(NPT + n) * DD];
        float prod = 1.f;
        #pragma unroll
        for (int k = 0; k < DIMX; k++) prod *= x2r[k];
        float payoff = powf(prod, 1.0f / (float)DIMX);
        payoff = fmaxf(payoff, 0.f);
        out[NPT + n] = g_FVAL[NPT + n] - payoff;
    }
}

extern "C" void kernel_launch(void* const* d_in, const int* in_sizes, int n_in,
                              void* d_out, int out_size)
{
    (void)in_sizes; (void)n_in; (void)out_size;
    const float* inputs = (const float*)d_in[0];
    const float* eps    = (const float*)d_in[1];
    const float* w1  = (const float*)d_in[2];
    const float* b1  = (const float*)d_in[3];
    const float* uzl = (const float*)d_in[4];
    const float* wzl = (const float*)d_in[5];
    const float* bzl = (const float*)d_in[6];
    const float* ugl = (const float*)d_in[7];
    const float* wgl = (const float*)d_in[8];
    const float* bgl = (const float*)d_in[9];
    const float* url = (const float*)d_in[10];
    const float* wrl = (const float*)d_in[11];
    const float* brl = (const float*)d_in[12];
    const float* uhl = (const float*)d_in[13];
    const float* whl = (const float*)d_in[14];
    const float* bhl = (const float*)d_in[15];
    const float* w   = (const float*)d_in[16];
    const float* b   = (const float*)d_in[17];
    float* out = (float*)d_out;

    const int smem_bytes = SM_TOT * (int)sizeof(float);
    static bool attr_set = false;
    if (!attr_set) {
        cudaFuncSetAttribute(dgm_main, cudaFuncAttributeMaxDynamicSharedMemorySize, smem_bytes);
        attr_set = true;
    }

    prep_kernel<<<64, 256>>>(wzl, wgl, wrl, whl, uzl, ugl, url, uhl, w1);
    build_kernel<<<BTOT / 256, 256>>>(inputs, eps);
    dgm_main<<<NTILES, THREADS, smem_bytes>>>(w1, b1, uzl, wzl, bzl, ugl, wgl, bgl,
                                              url, wrl, brl, uhl, whl, bhl, w, b);
    epilogue_kernel<<<NPT / 8, 256>>>(out);
}

// round 14
// speedup vs baseline: 1.3125x; 1.3125x over previous
#include <cuda_runtime.h>
#include <math.h>

#define DIMX   20
#define DD     21
#define NPT    2048
#define MCc    32
#define UNITS  128
#define TP     16
#define BTOT   69632
#define NTILES (BTOT / TP)
#define THREADS 512
#define NCTA   148

#define SIGc   0.2f
#define MUc    0.05f
#define Rc     0.05f
#define DELTAc 0.01f

__device__ float g_WT[4 * UNITS * UNITS];      // [mat][a][b] = W[b][a]
__device__ float g_UcatT[5 * UNITS * 24];      // [v][j][24] padded
__device__ float g_X[BTOT * DD];
__device__ float g_FP[BTOT * DD];
__device__ float g_FVAL[BTOT];
__device__ unsigned g_bar = 0;                 // monotonic grid barrier counter

// smem layout (floats) — identical to R9 best
#define SM_X    0                        // 336
#define SM_S    336                      // 3 * 2048
#define SM_Z    (SM_S + 3 * 2048)
#define SM_G    (SM_Z + 3 * 2048)
#define SM_R    (SM_G + 3 * 2048)
#define SM_H    (SM_R + 3 * 2048)
#define SM_SR   (SM_H + 3 * 2048)        // 2048 scratch (also chol L during build)
#define SM_FRED (SM_SR + 2048)           // 64
#define SM_TOT  (SM_FRED + 64)           // 33168 floats = 132672 B

typedef unsigned long long u64t;

__device__ __forceinline__ u64t pack2(float lo, float hi) {
    u64t r;
    asm("mov.b64 %0, {%1, %2};" : "=l"(r) : "f"(lo), "f"(hi));
    return r;
}
__device__ __forceinline__ float2 unpack2(u64t v) {
    float2 f;
    asm("mov.b64 {%0, %1}, %2;" : "=f"(f.x), "=f"(f.y) : "l"(v));
    return f;
}
__device__ __forceinline__ u64t ffma2(u64t a, u64t b, u64t c) {
    u64t d;
    asm("fma.rn.f32x2 %0, %1, %2, %3;" : "=l"(d) : "l"(a), "l"(b), "l"(c));
    return d;
}
__device__ __forceinline__ float ftanh(float x) {
    float ax = fabsf(x);
    float t = __expf(-2.0f * ax);
    float r = __fdividef(1.0f - t, 1.0f + t);
    return copysignf(r, x);
}

// grid barrier: monotonic counter, works across graph replays without reset
__device__ __forceinline__ void grid_barrier() {
    __syncthreads();
    if (threadIdx.x == 0) {
        __threadfence();
        unsigned old = atomicAdd(&g_bar, 1u);
        unsigned target = (old / NCTA + 1u) * NCTA;
        while (*(volatile unsigned*)&g_bar < target) { }
        __threadfence();
    }
    __syncthreads();
}

// ---- helpers (R9) ----
__device__ __forceinline__ void st4(float* dst, const float a[4], int j, int p0) {
    *(float4*)&dst[j * TP + p0] = make_float4(a[0], a[1], a[2], a[3]);
}
__device__ __forceinline__ void mm1(u64t& a0, u64t& a1, const float* __restrict__ W,
                                    const float* S, int j, int p0) {
    #pragma unroll 8
    for (int k = 0; k < UNITS; k++) {
        float wv = W[k * UNITS + j];
        u64t wp = pack2(wv, wv);
        ulonglong2 s = *(const ulonglong2*)&S[k * TP + p0];
        a0 = ffma2(s.x, wp, a0);
        a1 = ffma2(s.y, wp, a1);
    }
}
__device__ __forceinline__ void mmX(float acc[4], const float* __restrict__ U,
                                    const float* X, int j, int p0) {
    #pragma unroll
    for (int d = 0; d < DD; d++) {
        float wv = U[d * UNITS + j];
        float4 s = *(const float4*)&X[d * TP + p0];
        acc[0] += s.x * wv; acc[1] += s.y * wv; acc[2] += s.z * wv; acc[3] += s.w * wv;
    }
}
__device__ __forceinline__ void tanh4(float out[4], u64t a0, u64t a1) {
    float2 t0 = unpack2(a0), t1 = unpack2(a1);
    out[0] = ftanh(t0.x); out[1] = ftanh(t0.y); out[2] = ftanh(t1.x); out[3] = ftanh(t1.y);
}

__global__ __launch_bounds__(THREADS, 1)
void dgm_persistent(const float* __restrict__ inputs, const float* __restrict__ eps,
                    const float* __restrict__ w1, const float* __restrict__ b1,
                    const float* __restrict__ uz, const float* __restrict__ wz, const float* __restrict__ bz,
                    const float* __restrict__ ug, const float* __restrict__ wg, const float* __restrict__ bg,
                    const float* __restrict__ ur, const float* __restrict__ wr, const float* __restrict__ br,
                    const float* __restrict__ uh, const float* __restrict__ wh, const float* __restrict__ bh,
                    const float* __restrict__ wout, const float* __restrict__ bout,
                    float* __restrict__ out)
{
    extern __shared__ float sm[];
    const int tid = threadIdx.x;
    const int cta = blockIdx.x;
    const int gthread = cta * THREADS + tid;
    const int gstride = NCTA * THREADS;

    // ================= phase 0: prep (WT, UcatT) + build (X) =================
    for (int t = gthread; t < 4 * UNITS * UNITS; t += gstride) {
        int mat = t >> 14;
        int r   = t & 16383;
        int a   = r >> 7;
        int b   = r & 127;
        const float* W = (mat == 0) ? wz : (mat == 1) ? wg : (mat == 2) ? wr : wh;
        g_WT[t] = W[b * UNITS + a];
    }
    for (int t = gthread; t < 5 * UNITS * 24; t += gstride) {
        int v = t / (UNITS * 24);
        int r = t % (UNITS * 24);
        int jj = r / 24;
        int d = r % 24;
        const float* U = (v == 0) ? uz : (v == 1) ? ug : (v == 2) ? ur : (v == 3) ? uh : w1;
        g_UcatT[t] = (d < DD) ? U[d * UNITS + jj] : 0.0f;
    }

    // per-CTA cholesky into smem scratch (no cross-CTA dependency)
    if (tid == 0) {
        double Ld[DIMX][DIMX];
        for (int i = 0; i < DIMX; i++) {
            for (int j2 = 0; j2 <= i; j2++) {
                double s = 0.01 * (0.5 + (i == j2 ? 0.5 : 0.0));
                for (int k = 0; k < j2; k++) s -= Ld[i][k] * Ld[j2][k];
                Ld[i][j2] = (i == j2) ? sqrt(s) : s / Ld[j2][j2];
            }
        }
        for (int i = 0; i < DIMX; i++)
            for (int j2 = 0; j2 < DIMX; j2++)
                sm[SM_SR + i * DIMX + j2] = (j2 <= i) ? (float)Ld[i][j2] : 0.0f;
    }
    __syncthreads();
    const float* Lsm = &sm[SM_SR];

    for (int r = gthread; r < BTOT; r += gstride) {
        if (r < 4096) {
            #pragma unroll
            for (int d = 0; d < DD; d++) g_X[r * DD + d] = inputs[r * DD + d];
        } else {
            int q = r - 4096;
            int m = q >> 11;
            int n = q & 2047;
            float xr[DD];
            #pragma unroll
            for (int d = 0; d < DD; d++) xr[d] = inputs[n * DD + d];
            float e[DIMX];
            #pragma unroll
            for (int d = 0; d < DIMX; d++) e[d] = eps[(m * NPT + n) * DIMX + d];
            #pragma unroll
            for (int k = 0; k < DIMX; k++) {
                float acc = 0.f;
                #pragma unroll
                for (int d = 0; d < DIMX; d++) acc += e[d] * Lsm[k * DIMX + d];
                float sample = xr[k] + acc;
                float viol = sample * (SIGc * xr[k]);
                g_X[r * DD + k] = xr[k] + viol;
            }
            g_X[r * DD + DIMX] = xr[DIMX];
        }
    }

    grid_barrier();

    // ================= phase 1: main tile loop (R9 body) =================
    const int j  = tid & 127;
    const int pg = tid >> 7;
    const int p0 = pg * 4;

    for (int tile = cta; tile < NTILES; tile += NCTA) {
        const int base = tile * TP;
        const bool doGrad = !(tile >= 128 && tile < 256);

        __syncthreads();   // protect smem reuse across loop iterations
        for (int t = tid; t < TP * DD; t += THREADS) {
            int p = t / DD, d = t % DD;
            sm[SM_X + d * TP + p] = g_X[(base + p) * DD + d];
        }
        __syncthreads();

        // ---- prologue: x@U + b ----
        u64t xzr[2], xgr[2], xrr[2], xhr[2];
        float s_cur[4];
        {
            float acc[4];
            float bb;
            bb = bz[j];
            acc[0]=acc[1]=acc[2]=acc[3]=bb; mmX(acc, uz, &sm[SM_X], j, p0);
            xzr[0] = pack2(acc[0], acc[1]); xzr[1] = pack2(acc[2], acc[3]);
            bb = bg[j];
            acc[0]=acc[1]=acc[2]=acc[3]=bb; mmX(acc, ug, &sm[SM_X], j, p0);
            xgr[0] = pack2(acc[0], acc[1]); xgr[1] = pack2(acc[2], acc[3]);
            bb = br[j];
            acc[0]=acc[1]=acc[2]=acc[3]=bb; mmX(acc, ur, &sm[SM_X], j, p0);
            xrr[0] = pack2(acc[0], acc[1]); xrr[1] = pack2(acc[2], acc[3]);
            bb = bh[j];
            acc[0]=acc[1]=acc[2]=acc[3]=bb; mmX(acc, uh, &sm[SM_X], j, p0);
            xhr[0] = pack2(acc[0], acc[1]); xhr[1] = pack2(acc[2], acc[3]);
            bb = b1[j];
            acc[0]=acc[1]=acc[2]=acc[3]=bb; mmX(acc, w1, &sm[SM_X], j, p0);
            #pragma unroll
            for (int p = 0; p < 4; p++) s_cur[p] = ftanh(acc[p]);
            st4(&sm[SM_S + 0 * 2048], s_cur, j, p0);
        }
        __syncthreads();

        // ---- forward ----
        #pragma unroll 1
        for (int l = 0; l < 3; l++) {
            float* Sin = &sm[SM_S + l * 2048];
            float* ZA  = &sm[SM_Z + l * 2048];
            float* GA  = &sm[SM_G + l * 2048];
            float* RA  = &sm[SM_R + l * 2048];
            float* HA  = &sm[SM_H + l * 2048];
            float* SR  = &sm[SM_SR];

            float z4[4], g4[4], h4[4];
            {
                u64t az0 = xzr[0], az1 = xzr[1];
                u64t ag0 = xgr[0], ag1 = xgr[1];
                u64t ar0 = xrr[0], ar1 = xrr[1];
                #pragma unroll 4
                for (int k = 0; k < UNITS; k++) {
                    float wzv = wz[k * UNITS + j];
                    float wgv = wg[k * UNITS + j];
                    float wrv = wr[k * UNITS + j];
                    u64t wzp = pack2(wzv, wzv);
                    u64t wgp = pack2(wgv, wgv);
                    u64t wrp = pack2(wrv, wrv);
                    ulonglong2 s = *(const ulonglong2*)&Sin[k * TP + p0];
                    az0 = ffma2(s.x, wzp, az0); az1 = ffma2(s.y, wzp, az1);
                    ag0 = ffma2(s.x, wgp, ag0); ag1 = ffma2(s.y, wgp, ag1);
                    ar0 = ffma2(s.x, wrp, ar0); ar1 = ffma2(s.y, wrp, ar1);
                }
                float r4[4], sr4[4];
                tanh4(z4, az0, az1);
                tanh4(g4, ag0, ag1);
                tanh4(r4, ar0, ar1);
                st4(ZA, z4, j, p0);
                st4(GA, g4, j, p0);
                st4(RA, r4, j, p0);
                #pragma unroll
                for (int p = 0; p < 4; p++) sr4[p] = s_cur[p] * r4[p];
                st4(SR, sr4, j, p0);
            }
            __syncthreads();
            {
                u64t ah0 = xhr[0], ah1 = xhr[1];
                mm1(ah0, ah1, wh, SR, j, p0);
                tanh4(h4, ah0, ah1);
                st4(HA, h4, j, p0);
            }
            #pragma unroll
            for (int p = 0; p < 4; p++)
                s_cur[p] = (1.0f - g4[p]) * h4[p] + z4[p] * s_cur[p];
            if (l < 2) st4(&sm[SM_S + (l + 1) * 2048], s_cur, j, p0);
            __syncthreads();
        }

        // ---- value f = s3@w + b ----
        {
            float wv = wout[j];
            int warpId = tid >> 5;
            #pragma unroll
            for (int p = 0; p < 4; p++) {
                float v = wv * s_cur[p];
                #pragma unroll
                for (int off = 16; off; off >>= 1) v += __shfl_xor_sync(0xffffffffu, v, off);
                if ((tid & 31) == 0) sm[SM_FRED + warpId * 4 + p] = v;
            }
            __syncthreads();
            if (tid < TP) {
                int p = tid;
                int pgp = p >> 2;
                float f = bout[0];
                #pragma unroll
                for (int q = 0; q < 4; q++) f += sm[SM_FRED + (pgp * 4 + q) * 4 + (p & 3)];
                g_FVAL[base + p] = f;
            }
        }

        if (!doGrad) continue;

        // ---- backward ----
        float ds[4], Daz[4], Dag[4], Dar[4], Dah[4];
        {
            float wv = wout[j];
            #pragma unroll
            for (int p = 0; p < 4; p++) {
                ds[p] = wv;
                Daz[p] = 0.f; Dag[p] = 0.f; Dar[p] = 0.f; Dah[p] = 0.f;
            }
        }

        #pragma unroll 1
        for (int l = 2; l >= 0; l--) {
            float* Sin = &sm[SM_S + l * 2048];
            float* ZA  = &sm[SM_Z + l * 2048];
            float* GA  = &sm[SM_G + l * 2048];
            float* RA  = &sm[SM_R + l * 2048];
            float* HA  = &sm[SM_H + l * 2048];

            // stage A
            {
                float z4[4], g4[4], h4[4], sl4[4];
                {
                    float4 t;
                    t = *(const float4*)&ZA[j * TP + p0];  z4[0]=t.x; z4[1]=t.y; z4[2]=t.z; z4[3]=t.w;
                    t = *(const float4*)&GA[j * TP + p0];  g4[0]=t.x; g4[1]=t.y; g4[2]=t.z; g4[3]=t.w;
                    t = *(const float4*)&HA[j * TP + p0];  h4[0]=t.x; h4[1]=t.y; h4[2]=t.z; h4[3]=t.w;
                    t = *(const float4*)&Sin[j * TP + p0]; sl4[0]=t.x; sl4[1]=t.y; sl4[2]=t.z; sl4[3]=t.w;
                }
                float daz[4], dag[4], dah[4];
                #pragma unroll
                for (int p = 0; p < 4; p++) {
                    float dsp = ds[p];
                    float dh = dsp * (1.0f - g4[p]);
                    float dg = -dsp * h4[p];
                    float dz = dsp * sl4[p];
                    daz[p] = dz * (1.0f - z4[p] * z4[p]);
                    dag[p] = dg * (1.0f - g4[p] * g4[p]);
                    dah[p] = dh * (1.0f - h4[p] * h4[p]);
                    Daz[p] += daz[p]; Dag[p] += dag[p]; Dah[p] += dah[p];
                    ds[p] = dsp * z4[p];
                }
                st4(ZA, daz, j, p0);
                st4(GA, dag, j, p0);
                st4(HA, dah, j, p0);
            }
            __syncthreads();

            // stage B: dsr = dah @ Wh^T
            float dsr[4];
            {
                u64t b0 = pack2(0.f, 0.f), b1p = pack2(0.f, 0.f);
                mm1(b0, b1p, g_WT + 3 * UNITS * UNITS, HA, j, p0);
                float2 t0 = unpack2(b0), t1 = unpack2(b1p);
                dsr[0] = t0.x; dsr[1] = t0.y; dsr[2] = t1.x; dsr[3] = t1.y;
            }

            // stage C
            {
                float r4[4], sl4[4], dar[4];
                {
                    float4 t;
                    t = *(const float4*)&RA[j * TP + p0];  r4[0]=t.x; r4[1]=t.y; r4[2]=t.z; r4[3]=t.w;
                    t = *(const float4*)&Sin[j * TP + p0]; sl4[0]=t.x; sl4[1]=t.y; sl4[2]=t.z; sl4[3]=t.w;
                }
                #pragma unroll
                for (int p = 0; p < 4; p++) {
                    ds[p] += dsr[p] * r4[p];
                    dar[p] = (dsr[p] * sl4[p]) * (1.0f - r4[p] * r4[p]);
                    Dar[p] += dar[p];
                }
                st4(RA, dar, j, p0);
            }
            __syncthreads();

            // stage D: merged 3-matrix pass
            {
                const float* WzT = g_WT + 0 * UNITS * UNITS;
                const float* WgT = g_WT + 1 * UNITS * UNITS;
                const float* WrT = g_WT + 2 * UNITS * UNITS;
                u64t d0 = pack2(ds[0], ds[1]), d1 = pack2(ds[2], ds[3]);
                #pragma unroll 4
                for (int k = 0; k < UNITS; k++) {
                    float az = WzT[k * UNITS + j];
                    float ag = WgT[k * UNITS + j];
                    float ar = WrT[k * UNITS + j];
                    u64t azp = pack2(az, az);
                    u64t agp = pack2(ag, ag);
                    u64t arp = pack2(ar, ar);
                    ulonglong2 zz = *(const ulonglong2*)&ZA[k * TP + p0];
                    ulonglong2 gg = *(const ulonglong2*)&GA[k * TP + p0];
                    ulonglong2 rr = *(const ulonglong2*)&RA[k * TP + p0];
                    d0 = ffma2(zz.x, azp, d0); d1 = ffma2(zz.y, azp, d1);
                    d0 = ffma2(gg.x, agp, d0); d1 = ffma2(gg.y, agp, d1);
                    d0 = ffma2(rr.x, arp, d0); d1 = ffma2(rr.y, arp, d1);
                }
                float2 t0 = unpack2(d0), t1 = unpack2(d1);
                ds[0] = t0.x; ds[1] = t0.y; ds[2] = t1.x; ds[3] = t1.y;
            }
        }

        __syncthreads();
        {
            float da1[4], s04[4];
            {
                float4 t = *(const float4*)&sm[SM_S + j * TP + p0];
                s04[0]=t.x; s04[1]=t.y; s04[2]=t.z; s04[3]=t.w;
            }
            #pragma unroll
            for (int p = 0; p < 4; p++) da1[p] = ds[p] * (1.0f - s04[p] * s04[p]);
            st4(&sm[SM_Z], Daz, j, p0);
            st4(&sm[SM_G], Dag, j, p0);
            st4(&sm[SM_R], Dar, j, p0);
            st4(&sm[SM_H], Dah, j, p0);
            st4(&sm[SM_S], da1, j, p0);
        }
        __syncthreads();

        // dx = Σ_v Da_v @ U_v^T
        if (tid < DD * TP) {
            int d = tid % DD;
            int p = tid / DD;
            float acc = 0.f;
            #pragma unroll 1
            for (int v = 0; v < 5; v++) {
                const float* slot =
                    (v == 0) ? &sm[SM_Z] : (v == 1) ? &sm[SM_G] :
                    (v == 2) ? &sm[SM_R] : (v == 3) ? &sm[SM_H] : &sm[SM_S];
                const float* Ut = g_UcatT + v * UNITS * 24;
                #pragma unroll 8
                for (int k = 0; k < UNITS; k++)
                    acc += slot[k * TP + p] * Ut[k * 24 + d];
            }
            g_FP[base * DD + tid] = acc;
        }
    }

    grid_barrier();

    // ================= phase 2: epilogue =================
    {
        int warpId = tid >> 5;
        int lane   = tid & 31;
        int n = cta * 16 + warpId;     // 148*16 = 2368 warps >= 2048
        if (n < NPT) {
            const float* fp1 = &g_FP[n * DD];
            const float* x1r = &g_X[n * DD];
            int rp = (4096 + lane * NPT + n) * DD;
            const float* fpp = &g_FP[rp];
            const float* xp  = &g_X[rp];

            float part = 0.f;
            #pragma unroll
            for (int k = 0; k < DIMX; k++) {
                float viol = xp[k] - x1r[k];
                part += (fpp[k] - fp1[k]) * viol;
            }
            #pragma unroll
            for (int off = 16; off; off >>= 1) part += __shfl_xor_sync(0xffffffffu, part, off);

            if (lane == 0) {
                float term12 = part / (DELTAc * (float)MCc);
                float term11 = fp1[DIMX];
                #pragma unroll
                for (int k = 0; k < DIMX; k++) term11 += MUc * x1r[k] * fp1[k];
                out[n] = term11 + 0.5f * term12 - Rc * g_FVAL[n];

                const float* x2r = &g_X[(NPT + n) * DD];
                float prod = 1.f;
                #pragma unroll
                for (int k = 0; k < DIMX; k++) prod *= x2r[k];
                float payoff = powf(prod, 1.0f / (float)DIMX);
                payoff = fmaxf(payoff, 0.f);
                out[NPT + n] = g_FVAL[NPT + n] - payoff;
            }
        }
    }
}

extern "C" void kernel_launch(void* const* d_in, const int* in_sizes, int n_in,
                              void* d_out, int out_size)
{
    (void)in_sizes; (void)n_in; (void)out_size;
    const float* inputs = (const float*)d_in[0];
    const float* eps    = (const float*)d_in[1];
    const float* w1  = (const float*)d_in[2];
    const float* b1  = (const float*)d_in[3];
    const float* uzl = (const float*)d_in[4];
    const float* wzl = (const float*)d_in[5];
    const float* bzl = (const float*)d_in[6];
    const float* ugl = (const float*)d_in[7];
    const float* wgl = (const float*)d_in[8];
    const float* bgl = (const float*)d_in[9];
    const float* url = (const float*)d_in[10];
    const float* wrl = (const float*)d_in[11];
    const float* brl = (const float*)d_in[12];
    const float* uhl = (const float*)d_in[13];
    const float* whl = (const float*)d_in[14];
    const float* bhl = (const float*)d_in[15];
    const float* w   = (const float*)d_in[16];
    const float* b   = (const float*)d_in[17];
    float* out = (float*)d_out;

    const int smem_bytes = SM_TOT * (int)sizeof(float);
    cudaFuncSetAttribute(dgm_persistent, cudaFuncAttributeMaxDynamicSharedMemorySize, smem_bytes);

    dgm_persistent<<<NCTA, THREADS, smem_bytes>>>(
        inputs, eps, w1, b1, uzl, wzl, bzl, ugl, wgl, bgl,
        url, wrl, brl, uhl, whl, bhl, w, b, out);
}